// round 11
// baseline (speedup 1.0000x reference)
#include <cuda_runtime.h>
#include <cstdint>

// Problem constants (from reference): B=8, N=65536, C=256, NPOINT=1024
#define BB        8
#define NN        65536
#define CC        256
#define NPOINTS   1024
#define CHUNKS    16                  // CTAs per batch == cluster size
#define TFPS      512                 // threads per FPS block
#define NWARP     (TFPS / 32)
#define PPB       (NN / CHUNKS)       // 4096 points per block
#define PPT       (PPB / TFPS)        // 8 points per thread

__device__ int g_inds[BB][NPOINTS];   // fully rewritten every run -> no init needed

struct InitFar { int v[BB]; };

// ---------------------------------------------------------------------------
// PTX helpers
// ---------------------------------------------------------------------------
__device__ __forceinline__ uint32_t smem_u32(const void* p) {
    uint32_t a;
    asm("{ .reg .u64 t; cvta.to.shared.u64 t, %1; cvt.u32.u64 %0, t; }" : "=r"(a) : "l"(p));
    return a;
}
__device__ __forceinline__ uint32_t my_ctarank() {
    uint32_t r; asm("mov.u32 %0, %%cluster_ctarank;" : "=r"(r)); return r;
}
__device__ __forceinline__ uint32_t mapa_u32(uint32_t local, uint32_t rank) {
    uint32_t r;
    asm("mapa.shared::cluster.u32 %0, %1, %2;" : "=r"(r) : "r"(local), "r"(rank));
    return r;
}
__device__ __forceinline__ void st_dsmem_u64(uint32_t addr, unsigned long long v) {
    asm volatile("st.relaxed.cluster.shared::cluster.u64 [%0], %1;" :: "r"(addr), "l"(v) : "memory");
}
// Volatile LDS/STS: 29-cyc fast path; aligned 8B smem accesses are atomic.
__device__ __forceinline__ unsigned long long ld_smem_vol_u64(uint32_t addr) {
    unsigned long long v;
    asm volatile("ld.volatile.shared.u64 %0, [%1];" : "=l"(v) : "r"(addr) : "memory");
    return v;
}
__device__ __forceinline__ void st_smem_vol_u64(uint32_t addr, unsigned long long v) {
    asm volatile("st.volatile.shared.u64 [%0], %1;" :: "r"(addr), "l"(v) : "memory");
}
__device__ __forceinline__ unsigned ld_smem_vol_u32(uint32_t addr) {
    unsigned v;
    asm volatile("ld.volatile.shared.u32 %0, [%1];" : "=r"(v) : "r"(addr) : "memory");
    return v;
}
__device__ __forceinline__ void st_smem_vol_u32(uint32_t addr, unsigned v) {
    asm volatile("st.volatile.shared.u32 [%0], %1;" :: "r"(addr), "r"(v) : "memory");
}
__device__ __forceinline__ unsigned redux_max_u32(unsigned v) {
    unsigned r;
    asm volatile("redux.sync.max.u32 %0, %1, 0xffffffff;" : "=r"(r) : "r"(v));
    return r;
}
__device__ __forceinline__ void cluster_sync_all() {
    asm volatile("barrier.cluster.arrive.aligned;" ::: "memory");
    asm volatile("barrier.cluster.wait.aligned;"   ::: "memory");
}

// Two-stage argmax on (dist, key) via redux.sync.max — identical ordering to
// a u64 (dist<<32|key) max: dist primary, then larger key (keys derive from
// ~idx, so larger key == smaller index == jnp.argmax first-occurrence).
__device__ __forceinline__ void redux_argmax(unsigned d, unsigned k,
                                             unsigned* md, unsigned* wk) {
    const unsigned m = redux_max_u32(d);
    const unsigned c = (d == m) ? k : 0u;
    *md = m;
    *wk = redux_max_u32(c);
}

// ---------------------------------------------------------------------------
// FPS: one batch = one 16-CTA cluster; BARRIER-FREE iteration body.
// All synchronization is tagged single-writer/single-reader mailboxes:
//   s_red[w]  (smem, u64): warp w's (dist,key), parity tag (it&1) in bit 31
//             of the low word. Warps run at most 1 iteration ahead (they need
//             s_far@it first), so parity disambiguates fresh vs stale.
//   cluster slots (DSMEM): unchanged proven protocol — double buffer (it&1)
//             + phase tag ((it>>1)&1), peers at most 1 iteration ahead.
//   s_far     (smem, u32): far | (it<<16); every warp spins until tag == it.
// Chain: compute -> warp redux -> STS s_red -> warp0 polls 16 slots ->
// redux -> DSMEM all-to-all -> poll own slots -> redux -> STS s_far ->
// warps resume. No __syncthreads, no atomics, no fences in the loop.
// ---------------------------------------------------------------------------
__global__ __launch_bounds__(TFPS, 1) __cluster_dims__(CHUNKS, 1, 1)
void fps_kernel(const float* __restrict__ xyz, InitFar init) {
    const int b    = blockIdx.y;
    const int t    = threadIdx.x;
    const int lane = t & 31;
    const int warp = t >> 5;
    const uint32_t rank = my_ctarank();          // == blockIdx.x
    const int base = (int)rank * PPB;

    __shared__ unsigned long long s_slots[2][CHUNKS];   // cluster mailbox
    __shared__ unsigned long long s_red[NWARP];         // intra-CTA warp mailbox
    __shared__ unsigned s_far;                          // tagged broadcast

    // Initialize tags to "invalid" for the first iterations
    if (t < 2 * CHUNKS) s_slots[t >> 4][t & 15] = 0x80000000ull;  // phase=1, iters 0/1 expect 0
    if (t < NWARP)      s_red[t] = 0x80000000ull;                 // parity=1, iter 0 expects 0
    if (t == 0)         s_far = 0xFFFF0000u;                      // tag 0xFFFF != it 0

    const float* __restrict__ xb = xyz + (size_t)b * NN * 3;

    float    px[PPT], py[PPT], pz[PPT], dist[PPT];
    unsigned ienc[PPT];
#pragma unroll
    for (int k = 0; k < PPT; ++k) {
        const int p = base + k * TFPS + t;
        const float* q = xb + 3 * (size_t)p;
        px[k] = q[0]; py[k] = q[1]; pz[k] = q[2];
        dist[k] = 1e10f;
        ienc[k] = ~(unsigned)p;
    }

    // Precomputed addresses
    const uint32_t a_red_mine = smem_u32(&s_red[warp]);            // producer store
    const uint32_t a_red_poll = smem_u32(&s_red[lane & (NWARP-1)]);// warp0 poll
    const uint32_t a_far      = smem_u32(&s_far);
    uint32_t st_addr[2], poll_addr[2];
    {
        const uint32_t l0 = smem_u32(&s_slots[0][rank]);
        const uint32_t l1 = smem_u32(&s_slots[1][rank]);
        const uint32_t peer = (lane < CHUNKS) ? (uint32_t)lane : 0u;
        st_addr[0] = mapa_u32(l0, peer);          // my value -> peer's slot[buf][rank]
        st_addr[1] = mapa_u32(l1, peer);
        poll_addr[0] = smem_u32(&s_slots[0][lane & 15]);  // my own slot[buf][lane]
        poll_addr[1] = smem_u32(&s_slots[1][lane & 15]);
    }

    __syncthreads();
    cluster_sync_all();   // all CTAs' slot tags initialized before any publish

    int far = init.v[b];

    for (int it = 0; it < NPOINTS; ++it) {
        const int buf = it & 1;
        const unsigned ptag  = (unsigned)(it & 1);         // intra-CTA parity tag
        const unsigned phase = (unsigned)((it >> 1) & 1);  // cluster phase tag

        if (rank == 0 && t == 0) g_inds[b][it] = far;      // lax.scan pre-update index

        // Centroid broadcast load (L2 hit; L1 after first warp)
        const float* cq = xb + 3 * (size_t)far;
        const float cx = __ldg(cq + 0);
        const float cy = __ldg(cq + 1);
        const float cz = __ldg(cq + 2);

        float    bd = -1.0f;
        unsigned bi = 0u;
#pragma unroll
        for (int k = 0; k < PPT; ++k) {
            // Match XLA (no FP contraction): sub, mul, (d0+d1)+d2, all RN
            const float dx = __fsub_rn(px[k], cx);
            const float dy = __fsub_rn(py[k], cy);
            const float dz = __fsub_rn(pz[k], cz);
            const float d  = __fadd_rn(__fadd_rn(__fmul_rn(dx, dx), __fmul_rn(dy, dy)),
                                       __fmul_rn(dz, dz));
            const float nd = fminf(dist[k], d);
            dist[k] = nd;
            if (nd > bd) { bd = nd; bi = ienc[k]; }        // strict > keeps smallest idx
        }

        // Warp argmax via 2x redux; publish tagged (d,k) to this warp's slot
        unsigned m0, w0;
        redux_argmax(__float_as_uint(bd), bi, &m0, &w0);

        if (warp != 0) {
            if (lane == 0) {
                const unsigned long long v =
                    ((unsigned long long)m0 << 32)
                    | (unsigned long long)((w0 & 0x7FFFFFFFu) | (ptag << 31));
                st_smem_vol_u64(a_red_mine, v);
            }
            // Spin until warp 0 broadcasts this iteration's winner
            unsigned fv;
            do { fv = ld_smem_vol_u32(a_far); } while ((fv >> 16) != (unsigned)it);
            far = (int)(fv & 0xFFFFu);
        } else {
            if (lane == 0) {
                const unsigned long long v =
                    ((unsigned long long)m0 << 32)
                    | (unsigned long long)((w0 & 0x7FFFFFFFu) | (ptag << 31));
                st_smem_vol_u64(a_red_mine, v);
            }

            // Poll the 16 warp slots (lane i watches s_red[i])
            unsigned long long v = 0ull;
            bool done = (lane >= NWARP);
            for (;;) {
                if (!done) {
                    v = ld_smem_vol_u64(a_red_poll);
                    done = (((unsigned)(v >> 31)) & 1u) == ptag;
                }
                if (__ballot_sync(0xFFFFFFFFu, done) == 0xFFFFFFFFu) break;
            }

            // Block argmax via 2x redux
            unsigned d2 = 0u, k2 = 0u;
            if (lane < NWARP) { d2 = (unsigned)(v >> 32); k2 = (unsigned)v; }
            unsigned m2, w2;
            redux_argmax(d2, k2, &m2, &w2);

            // Publish block winner to every CTA's slot[buf][rank]
            const unsigned long long blk =
                ((unsigned long long)m2 << 32)
                | (unsigned long long)((w2 & 0x7FFFFFFFu) | (phase << 31));
            if (lane < CHUNKS) st_dsmem_u64(st_addr[buf], blk);

            // Poll own cluster slots (lane r watches slot[buf][r])
            unsigned long long cv = 0ull;
            bool cdone = (lane >= CHUNKS);
            for (;;) {
                if (!cdone) {
                    cv = ld_smem_vol_u64(poll_addr[buf]);
                    cdone = (((unsigned)(cv >> 31)) & 1u) == phase;
                }
                if (__ballot_sync(0xFFFFFFFFu, cdone) == 0xFFFFFFFFu) break;
            }

            // Cluster argmax via 2x redux
            unsigned d3 = 0u, k3 = 0u;
            if (lane < CHUNKS) { d3 = (unsigned)(cv >> 32); k3 = (unsigned)cv; }
            unsigned m3, w3;
            redux_argmax(d3, k3, &m3, &w3);

            far = (int)((~w3) & 0xFFFFu);
            if (lane == 0)
                st_smem_vol_u32(a_far, (unsigned)far | ((unsigned)it << 16));
        }
    }

    cluster_sync_all();   // no CTA exits while peers might still address its SMEM
}

// ---------------------------------------------------------------------------
// Gather outputs. d_out (float32) layout, concatenated in reference order:
//   [0)                    new_xyz      (B, NPOINT, 3)
//   [B*NPOINT*3)           new_features (B, C, NPOINT)
//   [.. + B*C*NPOINT)      sample_inds  (B, NPOINT)  (indices as float)
// ---------------------------------------------------------------------------
__global__ void gather_kernel(const float* __restrict__ xyz,
                              const float* __restrict__ feat,
                              float* __restrict__ out) {
    const int b = blockIdx.x;
    const int c = blockIdx.y;

    float* out_xyz  = out;
    float* out_feat = out + (size_t)BB * NPOINTS * 3;
    float* out_inds = out_feat + (size_t)BB * CC * NPOINTS;

    const float* frow = feat + ((size_t)b * CC + c) * NN;
    float*       orow = out_feat + ((size_t)b * CC + c) * NPOINTS;

    for (int j = threadIdx.x; j < NPOINTS; j += blockDim.x) {
        const int idx = g_inds[b][j];
        orow[j] = __ldg(frow + idx);
        if (c == 0) {
            out_inds[(size_t)b * NPOINTS + j] = (float)idx;
            const float* q = xyz + ((size_t)b * NN + idx) * 3;
            float* o = out_xyz + ((size_t)b * NPOINTS + j) * 3;
            o[0] = __ldg(q + 0); o[1] = __ldg(q + 1); o[2] = __ldg(q + 2);
        }
    }
}

// ---------------------------------------------------------------------------
// Host: reproduce jax.random.randint(jax.random.key(1), (8,), 0, 65536)
// under jax_threefry_partitionable=True (default since JAX 0.5.0).
//   k1, k2 = split(key(1));  lower = random_bits(k2, 32, (8,));  idx = lower & 0xFFFF
//   split:       newkey_j = threefry2x32((0,1), (0, j))
//   random_bits: bits[b]  = o0 ^ o1 of threefry2x32(k2, (0, b))
// ---------------------------------------------------------------------------
static void threefry2x32_host(uint32_t k0, uint32_t k1, uint32_t c0, uint32_t c1,
                              uint32_t* o0, uint32_t* o1) {
    const uint32_t ks[3] = { k0, k1, k0 ^ k1 ^ 0x1BD11BDAu };
    static const int rot0[4] = {13, 15, 26, 6};
    static const int rot1[4] = {17, 29, 16, 24};
    uint32_t x0 = c0 + ks[0];
    uint32_t x1 = c1 + ks[1];
    for (int i = 0; i < 5; ++i) {
        const int* rr = (i % 2 == 0) ? rot0 : rot1;
        for (int j = 0; j < 4; ++j) {
            x0 += x1;
            x1 = (x1 << rr[j]) | (x1 >> (32 - rr[j]));
            x1 ^= x0;
        }
        x0 += ks[(i + 1) % 3];
        x1 += ks[(i + 2) % 3] + (uint32_t)(i + 1);
    }
    *o0 = x0; *o1 = x1;
}

extern "C" void kernel_launch(void* const* d_in, const int* in_sizes, int n_in,
                              void* d_out, int out_size) {
    (void)in_sizes; (void)n_in; (void)out_size;
    const float* xyz  = (const float*)d_in[0];
    const float* feat = (const float*)d_in[1];

    uint32_t k2a, k2b;
    threefry2x32_host(0u, 1u, 0u, 1u, &k2a, &k2b);   // k2 = second split of key(1)

    InitFar init;
    for (int b = 0; b < BB; ++b) {
        uint32_t o0, o1;
        threefry2x32_host(k2a, k2b, 0u, (uint32_t)b, &o0, &o1);
        init.v[b] = (int)((o0 ^ o1) & 0xFFFFu);
    }

    // 16-CTA clusters require the non-portable opt-in (idempotent, not captured)
    cudaFuncSetAttribute(fps_kernel, cudaFuncAttributeNonPortableClusterSizeAllowed, 1);

    fps_kernel<<<dim3(CHUNKS, BB), TFPS>>>(xyz, init);
    gather_kernel<<<dim3(BB, CC), 256>>>(xyz, feat, (float*)d_out);
}